// round 6
// baseline (speedup 1.0000x reference)
#include <cuda_runtime.h>
#include <cuda_bf16.h>
#include <math.h>
#include <float.h>

#define N_NODES 50000
#define N_EDGES 1600000
#define N_MSG   (N_EDGES + N_NODES)
#define C_OUT   40

// ---------------- scratch (static device globals; no allocation) ----------------
__device__ __align__(256) unsigned int g_agg_u[N_NODES * 64]; // mapped-uint segment-max
__device__ __align__(256) float g_g1 [N_NODES * 128];    // after W3+relu
__device__ __align__(256) float g_g2 [N_NODES * 1024];   // after W4+relu
__device__ __align__(256) float g_g3 [N_NODES * 64];     // after W5 (no relu)

// ---------------- helpers ----------------
// Monotone float<->uint order map: f(a) < f(b) iff a < b (as floats).
__device__ __forceinline__ unsigned int fmap(float v) {
    unsigned int k = __float_as_uint(v);
    return ((int)k < 0) ? ~k : (k | 0x80000000u);
}
__device__ __forceinline__ float funmap(unsigned int k) {
    return (k & 0x80000000u) ? __uint_as_float(k & 0x7FFFFFFFu)
                             : __uint_as_float(~k);
}

__device__ __forceinline__ unsigned int f2tf32(float f) {
    unsigned int u;
    asm("cvt.rna.tf32.f32 %0, %1;" : "=r"(u) : "f"(f));
    return u;
}

__device__ __forceinline__ void mma_tf32(float (&c)[4],
                                         unsigned int a0, unsigned int a1,
                                         unsigned int a2, unsigned int a3,
                                         unsigned int b0, unsigned int b1) {
    asm volatile(
        "mma.sync.aligned.m16n8k8.row.col.f32.tf32.tf32.f32 "
        "{%0,%1,%2,%3}, {%4,%5,%6,%7}, {%8,%9}, {%0,%1,%2,%3};"
        : "+f"(c[0]), "+f"(c[1]), "+f"(c[2]), "+f"(c[3])
        : "r"(a0), "r"(a1), "r"(a2), "r"(a3), "r"(b0), "r"(b1));
}

// ---------------- kernel 1: fused edge MLP + atomic segment-max ----------------
__global__ __launch_bounds__(256) void k_edge(
    const float* __restrict__ x,          // [N,3]
    const float* __restrict__ pos,        // [N,3]
    const int*   __restrict__ ei,         // [2,E] int32
    const float* __restrict__ W1,         // [6,64]
    const float* __restrict__ b1,         // [64]
    const float* __restrict__ W2,         // [64,64]
    const float* __restrict__ b2)         // [64]
{
    __shared__ float sW1[6 * 64];
    __shared__ float sb1[64];
    __shared__ float sW2[64 * 64];
    __shared__ float sb2[64];

    for (int i = threadIdx.x; i < 6 * 64; i += blockDim.x) sW1[i] = W1[i];
    for (int i = threadIdx.x; i < 64; i += blockDim.x) { sb1[i] = b1[i]; sb2[i] = b2[i]; }
    for (int i = threadIdx.x; i < 64 * 64; i += blockDim.x) sW2[i] = W2[i];
    __syncthreads();

    int m = blockIdx.x * blockDim.x + threadIdx.x;
    if (m >= N_MSG) return;

    int src, dst;
    if (m < N_EDGES) {
        src = ei[m];
        dst = ei[N_EDGES + m];
    } else {
        src = dst = m - N_EDGES;   // self-loop
    }

    float in[6];
    in[0] = x[src * 3 + 0];
    in[1] = x[src * 3 + 1];
    in[2] = x[src * 3 + 2];
    in[3] = pos[src * 3 + 0] - pos[dst * 3 + 0];
    in[4] = pos[src * 3 + 1] - pos[dst * 3 + 1];
    in[5] = pos[src * 3 + 2] - pos[dst * 3 + 2];

    float acc[64];
    #pragma unroll
    for (int o = 0; o < 64; o++) acc[o] = sb2[o];

    for (int k = 0; k < 64; k++) {
        float h = sb1[k];
        #pragma unroll
        for (int i = 0; i < 6; i++) h = fmaf(in[i], sW1[i * 64 + k], h);
        h = fmaxf(h, 0.0f);
        const float4* wrow = (const float4*)(sW2 + k * 64);
        #pragma unroll
        for (int o4 = 0; o4 < 16; o4++) {
            float4 w = wrow[o4];
            acc[o4 * 4 + 0] = fmaf(h, w.x, acc[o4 * 4 + 0]);
            acc[o4 * 4 + 1] = fmaf(h, w.y, acc[o4 * 4 + 1]);
            acc[o4 * 4 + 2] = fmaf(h, w.z, acc[o4 * 4 + 2]);
            acc[o4 * 4 + 3] = fmaf(h, w.w, acc[o4 * 4 + 3]);
        }
    }

    unsigned int* dstp = g_agg_u + (size_t)dst * 64;
    #pragma unroll
    for (int o = 0; o < 64; o++) atomicMax(dstp + o, fmap(acc[o]));
}

// ---------------- tf32 tensor-core GEMM: C = act(A @ W + b) ----------------
// Block tile 128x64, BK=32, 256 threads = 8 warps in 4(M) x 2(N) grid.
// Warp tile 32x32 = 2(m16) x 4(n8) mma tiles, k8 steps.
// UNMAP: A is uint-mapped (segment-max output), unmap on load.
template<int K_TOT, int NOUT, bool RELU_OUT, bool UNMAP>
__global__ __launch_bounds__(256) void k_gemm_tf32(
    const void* __restrict__ Av,   // [nrows, K_TOT] float or mapped-uint
    const float* __restrict__ W,   // [K_TOT, NOUT]
    const float* __restrict__ b,   // [NOUT]
    float* __restrict__ C,         // [nrows, NOUT]
    int nrows)
{
    __shared__ unsigned int As[128][36];   // [m][k], pad->stride 36 (conflict-free)
    __shared__ unsigned int Bs[32][68];    // [k][n], stride 68 (conflict-free)

    const int tid  = threadIdx.x;
    const int lane = tid & 31;
    const int warp = tid >> 5;
    const int wm   = warp >> 1;            // 0..3 (M)
    const int wn   = warp & 1;             // 0..1 (N)
    const int g    = lane >> 2;            // 0..7
    const int tg   = lane & 3;             // 0..3

    const int n0 = blockIdx.x * 128;
    const int o0 = blockIdx.y * 64;

    const float* Af = (const float*)Av;
    const unsigned int* Au = (const unsigned int*)Av;

    float acc[2][4][4];
    #pragma unroll
    for (int mt = 0; mt < 2; mt++)
        #pragma unroll
        for (int nt = 0; nt < 4; nt++)
            #pragma unroll
            for (int q = 0; q < 4; q++) acc[mt][nt][q] = 0.0f;

    const int kk = tid & 31;        // A load k
    const int nr = tid >> 5;        // A load row-group 0..7
    const int oo = tid & 63;        // B load n
    const int kb = tid >> 6;        // B load k-group 0..3

    for (int k0 = 0; k0 < K_TOT; k0 += 32) {
        // A tile: As[m][kk] = tf32(A[n0+m][k0+kk])
        #pragma unroll
        for (int jj = 0; jj < 16; jj++) {
            int m = nr * 16 + jj;
            int row = n0 + m;
            float v = 0.0f;
            if (row < nrows) {
                size_t idx = (size_t)row * K_TOT + k0 + kk;
                v = UNMAP ? funmap(Au[idx]) : Af[idx];
            }
            As[m][kk] = f2tf32(v);
        }
        // B tile: Bs[k][oo] = tf32(W[(k0+k)*NOUT + o0+oo])
        #pragma unroll
        for (int jj = 0; jj < 8; jj++) {
            int k = kb * 8 + jj;
            Bs[k][oo] = f2tf32(W[(size_t)(k0 + k) * NOUT + o0 + oo]);
        }
        __syncthreads();

        #pragma unroll
        for (int ks = 0; ks < 4; ks++) {
            const int kbase = ks * 8;
            unsigned int af[2][4];
            #pragma unroll
            for (int mt = 0; mt < 2; mt++) {
                int mrow = wm * 32 + mt * 16;
                af[mt][0] = As[mrow + g    ][kbase + tg    ];
                af[mt][1] = As[mrow + g + 8][kbase + tg    ];
                af[mt][2] = As[mrow + g    ][kbase + tg + 4];
                af[mt][3] = As[mrow + g + 8][kbase + tg + 4];
            }
            #pragma unroll
            for (int nt = 0; nt < 4; nt++) {
                int ncol = wn * 32 + nt * 8 + g;
                unsigned int b0 = Bs[kbase + tg    ][ncol];
                unsigned int b1 = Bs[kbase + tg + 4][ncol];
                #pragma unroll
                for (int mt = 0; mt < 2; mt++)
                    mma_tf32(acc[mt][nt], af[mt][0], af[mt][1], af[mt][2], af[mt][3], b0, b1);
            }
        }
        __syncthreads();
    }

    // Epilogue: bias + optional relu, float2 stores.
    #pragma unroll
    for (int nt = 0; nt < 4; nt++) {
        int c = o0 + wn * 32 + nt * 8 + 2 * tg;
        float bv0 = b[c];
        float bv1 = b[c + 1];
        #pragma unroll
        for (int mt = 0; mt < 2; mt++) {
            int r0 = n0 + wm * 32 + mt * 16 + g;
            #pragma unroll
            for (int half = 0; half < 2; half++) {
                int r = r0 + half * 8;
                if (r >= nrows) continue;
                float v0 = acc[mt][nt][half * 2 + 0] + bv0;
                float v1 = acc[mt][nt][half * 2 + 1] + bv1;
                if (RELU_OUT) { v0 = fmaxf(v0, 0.0f); v1 = fmaxf(v1, 0.0f); }
                float2 st; st.x = v0; st.y = v1;
                *(float2*)&C[(size_t)r * NOUT + c] = st;
            }
        }
    }
}

// ---------------- kernel: relu(g3) @ Wf + bf, then log_softmax ----------------
__global__ __launch_bounds__(256) void k_fc_softmax(
    const float* __restrict__ Wf,  // [64,40]
    const float* __restrict__ bf,  // [40]
    float* __restrict__ out)       // [N,40]
{
    __shared__ float sWf[64 * 40];
    __shared__ float sbf[40];
    for (int i = threadIdx.x; i < 64 * 40; i += blockDim.x) sWf[i] = Wf[i];
    for (int i = threadIdx.x; i < 40; i += blockDim.x) sbf[i] = bf[i];
    __syncthreads();

    int warp = threadIdx.x >> 5;
    int lane = threadIdx.x & 31;
    int node = blockIdx.x * 8 + warp;
    if (node >= N_NODES) return;

    const float* gp = g_g3 + (size_t)node * 64;
    float v0 = sbf[lane];
    float v1 = (lane < 8) ? sbf[lane + 32] : -FLT_MAX;

    for (int k = 0; k < 64; k++) {
        float a = fmaxf(gp[k], 0.0f);
        v0 = fmaf(a, sWf[k * 40 + lane], v0);
        if (lane < 8) v1 = fmaf(a, sWf[k * 40 + lane + 32], v1);
    }

    float m = fmaxf(v0, v1);
    #pragma unroll
    for (int off = 16; off > 0; off >>= 1)
        m = fmaxf(m, __shfl_xor_sync(0xFFFFFFFFu, m, off));

    float s = __expf(v0 - m) + ((lane < 8) ? __expf(v1 - m) : 0.0f);
    #pragma unroll
    for (int off = 16; off > 0; off >>= 1)
        s += __shfl_xor_sync(0xFFFFFFFFu, s, off);

    float ls = __logf(s);
    float* op = out + (size_t)node * 40;
    op[lane] = v0 - m - ls;
    if (lane < 8) op[lane + 32] = v1 - m - ls;
}

// ---------------- launcher ----------------
extern "C" void kernel_launch(void* const* d_in, const int* in_sizes, int n_in,
                              void* d_out, int out_size) {
    const float* x   = (const float*)d_in[0];
    const float* pos = (const float*)d_in[1];
    const int*   ei  = (const int*)d_in[2];
    const float* W1 = (const float*)d_in[3];
    const float* b1 = (const float*)d_in[4];
    const float* W2 = (const float*)d_in[5];
    const float* b2 = (const float*)d_in[6];
    const float* W3 = (const float*)d_in[7];
    const float* b3 = (const float*)d_in[8];
    const float* W4 = (const float*)d_in[9];
    const float* b4 = (const float*)d_in[10];
    const float* W5 = (const float*)d_in[11];
    const float* b5 = (const float*)d_in[12];
    const float* Wf = (const float*)d_in[13];
    const float* bf = (const float*)d_in[14];
    float* out = (float*)d_out;

    void* aggp = nullptr; void* g1 = nullptr; void* g2 = nullptr; void* g3 = nullptr;
    cudaGetSymbolAddress(&aggp, g_agg_u);
    cudaGetSymbolAddress(&g1, g_g1);
    cudaGetSymbolAddress(&g2, g_g2);
    cudaGetSymbolAddress(&g3, g_g3);

    // mapped-uint 0 == below every mapped float -> acts as -inf init
    cudaMemsetAsync(aggp, 0, (size_t)N_NODES * 64 * sizeof(unsigned int));

    k_edge<<<(N_MSG + 255) / 256, 256>>>(x, pos, ei, W1, b1, W2, b2);

    dim3 grd3((N_NODES + 127) / 128, 128 / 64);
    k_gemm_tf32<64, 128, true, true><<<grd3, 256>>>(aggp, W3, b3, (float*)g1, N_NODES);

    dim3 grd4((N_NODES + 127) / 128, 1024 / 64);
    k_gemm_tf32<128, 1024, true, false><<<grd4, 256>>>(g1, W4, b4, (float*)g2, N_NODES);

    dim3 grd5((N_NODES + 127) / 128, 64 / 64);
    k_gemm_tf32<1024, 64, false, false><<<grd5, 256>>>(g2, W5, b5, (float*)g3, N_NODES);

    k_fc_softmax<<<(N_NODES + 7) / 8, 256>>>(Wf, bf, out);
}

// round 9
// speedup vs baseline: 1.8826x; 1.8826x over previous
#include <cuda_runtime.h>
#include <cuda_bf16.h>
#include <math.h>
#include <float.h>

#define N_NODES 50000
#define N_EDGES 1600000
#define N_MSG   (N_EDGES + N_NODES)
#define C_OUT   40

// ---------------- scratch (static device globals; no allocation) ----------------
__device__ __align__(256) unsigned int g_agg_u[N_NODES * 64]; // mapped-uint segment-max
__device__ __align__(256) float g_g1 [N_NODES * 128];
__device__ __align__(256) float g_g2 [N_NODES * 1024];
__device__ __align__(256) float g_g3 [N_NODES * 64];

// ---------------- helpers ----------------
// Monotone float<->uint order map: f(a) < f(b) iff a < b (as floats).
__device__ __forceinline__ unsigned int fmap(float v) {
    unsigned int k = __float_as_uint(v);
    return ((int)k < 0) ? ~k : (k | 0x80000000u);
}
__device__ __forceinline__ float funmap(unsigned int k) {
    return (k & 0x80000000u) ? __uint_as_float(k & 0x7FFFFFFFu)
                             : __uint_as_float(~k);
}
__device__ __forceinline__ unsigned int f2tf32(float f) {
    unsigned int u;
    asm("cvt.rna.tf32.f32 %0, %1;" : "=r"(u) : "f"(f));
    return u;
}
__device__ __forceinline__ void mma_tf32(float (&c)[4],
                                         unsigned int a0, unsigned int a1,
                                         unsigned int a2, unsigned int a3,
                                         unsigned int b0, unsigned int b1) {
    asm volatile(
        "mma.sync.aligned.m16n8k8.row.col.f32.tf32.tf32.f32 "
        "{%0,%1,%2,%3}, {%4,%5,%6,%7}, {%8,%9}, {%0,%1,%2,%3};"
        : "+f"(c[0]), "+f"(c[1]), "+f"(c[2]), "+f"(c[3])
        : "r"(a0), "r"(a1), "r"(a2), "r"(a3), "r"(b0), "r"(b1));
}

// ---------------- kernel 1: edge MLP, layer2 on tensor cores ----------------
// 128 messages per block. h1 = relu([x_j, pos_j-pos_i] @ W1 + b1) -> tf32 smem [k][msg].
// h = h1 @ W2 (mma) + b2; RED.MAX.U32 scatter into g_agg_u.
#define H1S 136  // h1s stride ([k][msg], 128 msgs + 8 pad): stores & frag reads conflict-free
#define W2S 72   // sW2t stride ([k][n]): frag reads conflict-free
__global__ __launch_bounds__(256) void k_edge_mma(
    const float* __restrict__ x,          // [N,3]
    const float* __restrict__ pos,        // [N,3]
    const int*   __restrict__ ei,         // [2,E] int32
    const float* __restrict__ W1,         // [6,64]
    const float* __restrict__ b1,         // [64]
    const float* __restrict__ W2,         // [64,64]
    const float* __restrict__ b2)         // [64]
{
    __shared__ float sW1[6 * 64];
    __shared__ float sb1[64];
    __shared__ float sb2[64];
    __shared__ unsigned int sW2t[64 * W2S];   // tf32, [k][n]
    __shared__ unsigned int h1s [64 * H1S];   // tf32, [k][msg]
    __shared__ int sdst[128];

    const int tid  = threadIdx.x;
    const int lane = tid & 31;
    const int warp = tid >> 5;

    for (int i = tid; i < 6 * 64; i += 256) sW1[i] = W1[i];
    if (tid < 64) { sb1[tid] = b1[tid]; sb2[tid] = b2[tid]; }
    for (int i = tid; i < 64 * 64; i += 256) {
        int k = i >> 6, n = i & 63;
        sW2t[k * W2S + n] = f2tf32(W2[i]);
    }
    __syncthreads();

    const int m0 = blockIdx.x * 128;
    const int ml = tid & 127;          // local message 0..127
    const int kh = tid >> 7;           // k-half 0/1
    const int m  = m0 + ml;

    int src = 0, dst = -1;
    if (m < N_MSG) {
        if (m < N_EDGES) { src = ei[m]; dst = ei[N_EDGES + m]; }
        else             { src = dst = m - N_EDGES; }          // self-loop
    }
    if (kh == 0) sdst[ml] = dst;

    float in[6];
    if (m < N_MSG) {
        in[0] = x[src * 3 + 0];
        in[1] = x[src * 3 + 1];
        in[2] = x[src * 3 + 2];
        in[3] = pos[src * 3 + 0] - pos[dst * 3 + 0];
        in[4] = pos[src * 3 + 1] - pos[dst * 3 + 1];
        in[5] = pos[src * 3 + 2] - pos[dst * 3 + 2];
    } else {
        #pragma unroll
        for (int i = 0; i < 6; i++) in[i] = 0.0f;
    }

    // layer 1: this thread covers k in [kh*32, kh*32+32) for its message
    #pragma unroll
    for (int j = 0; j < 32; j++) {
        int k = kh * 32 + j;
        float h = sb1[k];
        #pragma unroll
        for (int i = 0; i < 6; i++) h = fmaf(in[i], sW1[i * 64 + k], h);
        h = fmaxf(h, 0.0f);
        h1s[k * H1S + ml] = f2tf32(h);
    }
    __syncthreads();

    // layer 2 mma: warp w handles messages [w*16, w*16+16), all 64 channels
    const int g  = lane >> 2;
    const int tg = lane & 3;
    const int mrow = warp * 16;

    float c[8][4];
    #pragma unroll
    for (int nt = 0; nt < 8; nt++)
        #pragma unroll
        for (int q = 0; q < 4; q++) c[nt][q] = 0.0f;

    #pragma unroll
    for (int ks = 0; ks < 8; ks++) {
        const int k0 = ks * 8;
        unsigned int a0 = h1s[(k0 + tg    ) * H1S + mrow + g    ];
        unsigned int a1 = h1s[(k0 + tg    ) * H1S + mrow + g + 8];
        unsigned int a2 = h1s[(k0 + tg + 4) * H1S + mrow + g    ];
        unsigned int a3 = h1s[(k0 + tg + 4) * H1S + mrow + g + 8];
        #pragma unroll
        for (int nt = 0; nt < 8; nt++) {
            unsigned int b0 = sW2t[(k0 + tg    ) * W2S + nt * 8 + g];
            unsigned int b1 = sW2t[(k0 + tg + 4) * W2S + nt * 8 + g];
            mma_tf32(c[nt], a0, a1, a2, a3, b0, b1);
        }
    }

    // epilogue: +b2, RED.MAX.U32 scatter
    // accumulator rows: c[][0..1] -> msg mrow+g, c[][2..3] -> msg mrow+g+8; cols nt*8 + 2*tg (+1)
    const int d0 = sdst[mrow + g];
    const int d1 = sdst[mrow + g + 8];
    #pragma unroll
    for (int nt = 0; nt < 8; nt++) {
        int ch = nt * 8 + 2 * tg;
        float bv0 = sb2[ch], bv1 = sb2[ch + 1];
        if (d0 >= 0) {
            atomicMax(g_agg_u + (size_t)d0 * 64 + ch,     fmap(c[nt][0] + bv0));
            atomicMax(g_agg_u + (size_t)d0 * 64 + ch + 1, fmap(c[nt][1] + bv1));
        }
        if (d1 >= 0) {
            atomicMax(g_agg_u + (size_t)d1 * 64 + ch,     fmap(c[nt][2] + bv0));
            atomicMax(g_agg_u + (size_t)d1 * 64 + ch + 1, fmap(c[nt][3] + bv1));
        }
    }
}

// ---------------- proven fp32 register-tiled GEMM: C = act(A @ W + b) ----------------
template<int K_TOT, int NOUT, bool RELU_OUT, bool UNMAP>
__global__ __launch_bounds__(256) void k_mlp_gemm(
    const void* __restrict__ Av,   // [nrows, K_TOT] float or mapped-uint
    const float* __restrict__ W,   // [K_TOT, NOUT]
    const float* __restrict__ b,   // [NOUT]
    float* __restrict__ C,         // [nrows, NOUT]
    int nrows)
{
    __shared__ float As[32][129];   // k-major, padded
    __shared__ float Bs[32][64];

    const int tid = threadIdx.x;
    const int n0 = blockIdx.x * 128;
    const int o0 = blockIdx.y * 64;

    const int ot = tid & 15;
    const int nt = tid >> 4;

    const float* Af = (const float*)Av;
    const unsigned int* Au = (const unsigned int*)Av;

    float acc[8][4];
    #pragma unroll
    for (int j = 0; j < 8; j++)
        #pragma unroll
        for (int q = 0; q < 4; q++) acc[j][q] = 0.0f;

    const int kk = tid & 31;
    const int nr = tid >> 5;
    const int oo = tid & 63;
    const int kb = tid >> 6;

    for (int k0 = 0; k0 < K_TOT; k0 += 32) {
        #pragma unroll
        for (int jj = 0; jj < 16; jj++) {
            int n = nr * 16 + jj;
            int row = n0 + n;
            float v = 0.0f;
            if (row < nrows) {
                size_t idx = (size_t)row * K_TOT + k0 + kk;
                v = UNMAP ? funmap(Au[idx]) : Af[idx];
            }
            As[kk][n] = v;
        }
        #pragma unroll
        for (int jj = 0; jj < 8; jj++) {
            int k = kb * 8 + jj;
            Bs[k][oo] = W[(size_t)(k0 + k) * NOUT + o0 + oo];
        }
        __syncthreads();

        #pragma unroll
        for (int k = 0; k < 32; k++) {
            float4 wv = *(const float4*)&Bs[k][ot * 4];
            float av[8];
            #pragma unroll
            for (int j = 0; j < 8; j++) av[j] = As[k][nt * 8 + j];
            #pragma unroll
            for (int j = 0; j < 8; j++) {
                acc[j][0] = fmaf(av[j], wv.x, acc[j][0]);
                acc[j][1] = fmaf(av[j], wv.y, acc[j][1]);
                acc[j][2] = fmaf(av[j], wv.z, acc[j][2]);
                acc[j][3] = fmaf(av[j], wv.w, acc[j][3]);
            }
        }
        __syncthreads();
    }

    float bias0 = b[o0 + ot * 4 + 0];
    float bias1 = b[o0 + ot * 4 + 1];
    float bias2 = b[o0 + ot * 4 + 2];
    float bias3 = b[o0 + ot * 4 + 3];
    #pragma unroll
    for (int j = 0; j < 8; j++) {
        int row = n0 + nt * 8 + j;
        if (row >= nrows) continue;
        float4 v;
        v.x = acc[j][0] + bias0;
        v.y = acc[j][1] + bias1;
        v.z = acc[j][2] + bias2;
        v.w = acc[j][3] + bias3;
        if (RELU_OUT) {
            v.x = fmaxf(v.x, 0.0f); v.y = fmaxf(v.y, 0.0f);
            v.z = fmaxf(v.z, 0.0f); v.w = fmaxf(v.w, 0.0f);
        }
        *(float4*)&C[(size_t)row * NOUT + o0 + ot * 4] = v;
    }
}

// ---------------- kernel: relu(g3) @ Wf + bf, then log_softmax ----------------
__global__ __launch_bounds__(256) void k_fc_softmax(
    const float* __restrict__ Wf,  // [64,40]
    const float* __restrict__ bf,  // [40]
    float* __restrict__ out)       // [N,40]
{
    __shared__ float sWf[64 * 40];
    __shared__ float sbf[40];
    for (int i = threadIdx.x; i < 64 * 40; i += blockDim.x) sWf[i] = Wf[i];
    for (int i = threadIdx.x; i < 40; i += blockDim.x) sbf[i] = bf[i];
    __syncthreads();

    int warp = threadIdx.x >> 5;
    int lane = threadIdx.x & 31;
    int node = blockIdx.x * 8 + warp;
    if (node >= N_NODES) return;

    const float* gp = g_g3 + (size_t)node * 64;
    float v0 = sbf[lane];
    float v1 = (lane < 8) ? sbf[lane + 32] : -FLT_MAX;

    for (int k = 0; k < 64; k++) {
        float a = fmaxf(gp[k], 0.0f);
        v0 = fmaf(a, sWf[k * 40 + lane], v0);
        if (lane < 8) v1 = fmaf(a, sWf[k * 40 + lane + 32], v1);
    }

    float m = fmaxf(v0, v1);
    #pragma unroll
    for (int off = 16; off > 0; off >>= 1)
        m = fmaxf(m, __shfl_xor_sync(0xFFFFFFFFu, m, off));

    float s = __expf(v0 - m) + ((lane < 8) ? __expf(v1 - m) : 0.0f);
    #pragma unroll
    for (int off = 16; off > 0; off >>= 1)
        s += __shfl_xor_sync(0xFFFFFFFFu, s, off);

    float ls = __logf(s);
    float* op = out + (size_t)node * 40;
    op[lane] = v0 - m - ls;
    if (lane < 8) op[lane + 32] = v1 - m - ls;
}

// ---------------- launcher ----------------
extern "C" void kernel_launch(void* const* d_in, const int* in_sizes, int n_in,
                              void* d_out, int out_size) {
    const float* x   = (const float*)d_in[0];
    const float* pos = (const float*)d_in[1];
    const int*   ei  = (const int*)d_in[2];
    const float* W1 = (const float*)d_in[3];
    const float* b1 = (const float*)d_in[4];
    const float* W2 = (const float*)d_in[5];
    const float* b2 = (const float*)d_in[6];
    const float* W3 = (const float*)d_in[7];
    const float* b3 = (const float*)d_in[8];
    const float* W4 = (const float*)d_in[9];
    const float* b4 = (const float*)d_in[10];
    const float* W5 = (const float*)d_in[11];
    const float* b5 = (const float*)d_in[12];
    const float* Wf = (const float*)d_in[13];
    const float* bf = (const float*)d_in[14];
    float* out = (float*)d_out;

    void* aggp = nullptr; void* g1 = nullptr; void* g2 = nullptr; void* g3 = nullptr;
    cudaGetSymbolAddress(&aggp, g_agg_u);
    cudaGetSymbolAddress(&g1, g_g1);
    cudaGetSymbolAddress(&g2, g_g2);
    cudaGetSymbolAddress(&g3, g_g3);

    // mapped-uint 0 is below every mapped float -> -inf init
    cudaMemsetAsync(aggp, 0, (size_t)N_NODES * 64 * sizeof(unsigned int));

    k_edge_mma<<<(N_MSG + 127) / 128, 256>>>(x, pos, ei, W1, b1, W2, b2);

    dim3 grd3((N_NODES + 127) / 128, 128 / 64);
    k_mlp_gemm<64, 128, true, true><<<grd3, 256>>>(aggp, W3, b3, (float*)g1, N_NODES);

    dim3 grd4((N_NODES + 127) / 128, 1024 / 64);
    k_mlp_gemm<128, 1024, true, false><<<grd4, 256>>>(g1, W4, b4, (float*)g2, N_NODES);

    dim3 grd5((N_NODES + 127) / 128, 64 / 64);
    k_mlp_gemm<1024, 64, false, false><<<grd5, 256>>>(g2, W5, b5, (float*)g3, N_NODES);

    k_fc_softmax<<<(N_NODES + 7) / 8, 256>>>(Wf, bf, out);
}

// round 10
// speedup vs baseline: 3.0937x; 1.6433x over previous
#include <cuda_runtime.h>
#include <cuda_bf16.h>
#include <math.h>
#include <float.h>

#define N_NODES 50000
#define N_EDGES 1600000
#define N_MSG   (N_EDGES + N_NODES)
#define C_OUT   40

// ---------------- scratch (static device globals; no allocation) ----------------
__device__ __align__(256) unsigned int g_agg_u[N_NODES * 64]; // mapped-uint segment-max
__device__ __align__(256) float g_g1 [N_NODES * 128];
__device__ __align__(256) float g_g3 [N_NODES * 64];

// ---------------- helpers ----------------
// Monotone float<->uint order map: f(a) < f(b) iff a < b (as floats).
__device__ __forceinline__ unsigned int fmap(float v) {
    unsigned int k = __float_as_uint(v);
    return ((int)k < 0) ? ~k : (k | 0x80000000u);
}
__device__ __forceinline__ float funmap(unsigned int k) {
    return (k & 0x80000000u) ? __uint_as_float(k & 0x7FFFFFFFu)
                             : __uint_as_float(~k);
}
// NOTE: tf32 mma hardware reads only bits [31:13] of each operand register.
// Passing raw f32 bits == RZ-truncated tf32; we skip cvt.rna entirely.
__device__ __forceinline__ void mma_tf32(float (&c)[4],
                                         unsigned int a0, unsigned int a1,
                                         unsigned int a2, unsigned int a3,
                                         unsigned int b0, unsigned int b1) {
    asm volatile(
        "mma.sync.aligned.m16n8k8.row.col.f32.tf32.tf32.f32 "
        "{%0,%1,%2,%3}, {%4,%5,%6,%7}, {%8,%9}, {%0,%1,%2,%3};"
        : "+f"(c[0]), "+f"(c[1]), "+f"(c[2]), "+f"(c[3])
        : "r"(a0), "r"(a1), "r"(a2), "r"(a3), "r"(b0), "r"(b1));
}

// ---------------- kernel 1: edge MLP, layer2 on tensor cores ----------------
#define H1S 136  // h1s stride ([k][msg], 128 msgs + 8 pad)
#define W2S 72   // sW2t stride ([k][n])
__global__ __launch_bounds__(256) void k_edge_mma(
    const float* __restrict__ x,          // [N,3]
    const float* __restrict__ pos,        // [N,3]
    const int*   __restrict__ ei,         // [2,E] int32
    const float* __restrict__ W1,         // [6,64]
    const float* __restrict__ b1,         // [64]
    const float* __restrict__ W2,         // [64,64]
    const float* __restrict__ b2)         // [64]
{
    __shared__ float sW1[6 * 64];
    __shared__ float sb1[64];
    __shared__ float sb2[64];
    __shared__ unsigned int sW2t[64 * W2S];   // raw f32 bits, [k][n]
    __shared__ unsigned int h1s [64 * H1S];   // raw f32 bits, [k][msg]
    __shared__ int sdst[128];

    const int tid  = threadIdx.x;
    const int lane = tid & 31;
    const int warp = tid >> 5;

    for (int i = tid; i < 6 * 64; i += 256) sW1[i] = W1[i];
    if (tid < 64) { sb1[tid] = b1[tid]; sb2[tid] = b2[tid]; }
    for (int i = tid; i < 64 * 64; i += 256) {
        int k = i >> 6, n = i & 63;
        sW2t[k * W2S + n] = __float_as_uint(W2[i]);
    }
    __syncthreads();

    const int m0 = blockIdx.x * 128;
    const int ml = tid & 127;          // local message 0..127
    const int kh = tid >> 7;           // k-half 0/1
    const int m  = m0 + ml;

    int src = 0, dst = -1;
    if (m < N_MSG) {
        if (m < N_EDGES) { src = ei[m]; dst = ei[N_EDGES + m]; }
        else             { src = dst = m - N_EDGES; }          // self-loop
    }
    if (kh == 0) sdst[ml] = dst;

    float in[6];
    if (m < N_MSG) {
        in[0] = x[src * 3 + 0];
        in[1] = x[src * 3 + 1];
        in[2] = x[src * 3 + 2];
        in[3] = pos[src * 3 + 0] - pos[dst * 3 + 0];
        in[4] = pos[src * 3 + 1] - pos[dst * 3 + 1];
        in[5] = pos[src * 3 + 2] - pos[dst * 3 + 2];
    } else {
        #pragma unroll
        for (int i = 0; i < 6; i++) in[i] = 0.0f;
    }

    // layer 1: this thread covers k in [kh*32, kh*32+32) for its message
    #pragma unroll
    for (int j = 0; j < 32; j++) {
        int k = kh * 32 + j;
        float h = sb1[k];
        #pragma unroll
        for (int i = 0; i < 6; i++) h = fmaf(in[i], sW1[i * 64 + k], h);
        h = fmaxf(h, 0.0f);
        h1s[k * H1S + ml] = __float_as_uint(h);
    }
    __syncthreads();

    // layer 2 mma: warp w handles messages [w*16, w*16+16), all 64 channels
    const int g  = lane >> 2;
    const int tg = lane & 3;
    const int mrow = warp * 16;

    float c[8][4];
    #pragma unroll
    for (int nt = 0; nt < 8; nt++)
        #pragma unroll
        for (int q = 0; q < 4; q++) c[nt][q] = 0.0f;

    #pragma unroll
    for (int ks = 0; ks < 8; ks++) {
        const int k0 = ks * 8;
        unsigned int a0 = h1s[(k0 + tg    ) * H1S + mrow + g    ];
        unsigned int a1 = h1s[(k0 + tg    ) * H1S + mrow + g + 8];
        unsigned int a2 = h1s[(k0 + tg + 4) * H1S + mrow + g    ];
        unsigned int a3 = h1s[(k0 + tg + 4) * H1S + mrow + g + 8];
        #pragma unroll
        for (int nt = 0; nt < 8; nt++) {
            unsigned int b0 = sW2t[(k0 + tg    ) * W2S + nt * 8 + g];
            unsigned int b1 = sW2t[(k0 + tg + 4) * W2S + nt * 8 + g];
            mma_tf32(c[nt], a0, a1, a2, a3, b0, b1);
        }
    }

    // epilogue: +b2, RED.MAX.U32 scatter
    const int d0 = sdst[mrow + g];
    const int d1 = sdst[mrow + g + 8];
    #pragma unroll
    for (int nt = 0; nt < 8; nt++) {
        int ch = nt * 8 + 2 * tg;
        float bv0 = sb2[ch], bv1 = sb2[ch + 1];
        if (d0 >= 0) {
            atomicMax(g_agg_u + (size_t)d0 * 64 + ch,     fmap(c[nt][0] + bv0));
            atomicMax(g_agg_u + (size_t)d0 * 64 + ch + 1, fmap(c[nt][1] + bv1));
        }
        if (d1 >= 0) {
            atomicMax(g_agg_u + (size_t)d1 * 64 + ch,     fmap(c[nt][2] + bv0));
            atomicMax(g_agg_u + (size_t)d1 * 64 + ch + 1, fmap(c[nt][3] + bv1));
        }
    }
}

// ---------------- fused middle: g3 = relu(g1 @ W4 + b4) @ W5 + b5 ----------------
// 128 nodes/block, 256 threads, 8 warps (4M x 2N). Chunked over 1024 (8 x 128).
// g2 is never materialized. tf32 mma both stages; raw f32 bits as operands.
// smem word offsets:
#define FS_G1 0                     // [128m][132]  g1 tile      (stride 132 % 32 == 4)
#define FS_B  16896                 // W4 chunk [128k][136]  /  W5 chunk [128k][72]
#define FS_T  34304                 // [128m][132]  relu tile
#define FS_B4 51200                 // [128]
#define FS_B5 51328                 // [64]
#define FS_WORDS 51392              // 205,568 bytes dynamic smem

__global__ __launch_bounds__(256) void k_fused_mid(
    const float* __restrict__ A,    // g1 [nrows,128]
    const float* __restrict__ W4,   // [128,1024]
    const float* __restrict__ b4,   // [1024]
    const float* __restrict__ W5,   // [1024,64]
    const float* __restrict__ b5,   // [64]
    float* __restrict__ C,          // g3 [nrows,64]
    int nrows)
{
    extern __shared__ unsigned int sm[];
    const int tid  = threadIdx.x;
    const int lane = tid & 31;
    const int warp = tid >> 5;
    const int wm   = warp >> 1;        // 0..3
    const int wn   = warp & 1;         // 0..1
    const int g    = lane >> 2;        // 0..7
    const int tg   = lane & 3;         // 0..3
    const int mrow = wm * 32;
    const int n0   = blockIdx.x * 128;

    // load g1 tile (zero-fill past nrows)
    #pragma unroll
    for (int i = 0; i < 16; i++) {
        int idx = tid + i * 256;            // 0..4095
        int mm = idx >> 5, q = idx & 31;
        int row = n0 + mm;
        uint4 v = make_uint4(0u, 0u, 0u, 0u);
        if (row < nrows) v = *(const uint4*)&A[(size_t)row * 128 + q * 4];
        *(uint4*)&sm[FS_G1 + mm * 132 + q * 4] = v;
    }
    if (tid < 64) sm[FS_B5 + tid] = __float_as_uint(b5[tid]);

    float acc2[2][4][4];
    #pragma unroll
    for (int mt = 0; mt < 2; mt++)
        #pragma unroll
        for (int nt = 0; nt < 4; nt++)
            #pragma unroll
            for (int q = 0; q < 4; q++) acc2[mt][nt][q] = 0.0f;

    for (int cch = 0; cch < 8; cch++) {
        // ---- load W4 chunk + b4 chunk ----
        __syncthreads();   // prior stage2 readers of sB done
        #pragma unroll
        for (int i = 0; i < 16; i++) {
            int idx = tid + i * 256;
            int k = idx >> 5, q = idx & 31;
            *(uint4*)&sm[FS_B + k * 136 + q * 4] =
                *(const uint4*)&W4[(size_t)k * 1024 + cch * 128 + q * 4];
        }
        if (tid < 128) sm[FS_B4 + tid] = __float_as_uint(b4[cch * 128 + tid]);
        __syncthreads();

        // ---- stage1: t = g1_tile @ W4chunk  (128x128, K=128) ----
        float acc1[2][8][4];
        #pragma unroll
        for (int mt = 0; mt < 2; mt++)
            #pragma unroll
            for (int nt = 0; nt < 8; nt++)
                #pragma unroll
                for (int q = 0; q < 4; q++) acc1[mt][nt][q] = 0.0f;

        #pragma unroll
        for (int ks = 0; ks < 16; ks++) {
            const int k0 = ks * 8;
            unsigned int a[2][4];
            #pragma unroll
            for (int mt = 0; mt < 2; mt++) {
                int mr = mrow + mt * 16;
                a[mt][0] = sm[FS_G1 + (mr + g    ) * 132 + k0 + tg    ];
                a[mt][1] = sm[FS_G1 + (mr + g + 8) * 132 + k0 + tg    ];
                a[mt][2] = sm[FS_G1 + (mr + g    ) * 132 + k0 + tg + 4];
                a[mt][3] = sm[FS_G1 + (mr + g + 8) * 132 + k0 + tg + 4];
            }
            #pragma unroll
            for (int nt = 0; nt < 8; nt++) {
                int nc = wn * 64 + nt * 8 + g;
                unsigned int b0 = sm[FS_B + (k0 + tg    ) * 136 + nc];
                unsigned int b1 = sm[FS_B + (k0 + tg + 4) * 136 + nc];
                #pragma unroll
                for (int mt = 0; mt < 2; mt++)
                    mma_tf32(acc1[mt][nt], a[mt][0], a[mt][1], a[mt][2], a[mt][3], b0, b1);
            }
        }
        __syncthreads();   // all warps done reading sB (W4) and sG1 for this chunk

        // ---- bias + relu -> sT ; reload sB with W5 chunk ----
        #pragma unroll
        for (int nt = 0; nt < 8; nt++) {
            int col = wn * 64 + nt * 8 + 2 * tg;
            float bv0 = __uint_as_float(sm[FS_B4 + col]);
            float bv1 = __uint_as_float(sm[FS_B4 + col + 1]);
            #pragma unroll
            for (int mt = 0; mt < 2; mt++) {
                int r0 = mrow + mt * 16 + g;
                int r1 = r0 + 8;
                sm[FS_T + r0 * 132 + col    ] = __float_as_uint(fmaxf(acc1[mt][nt][0] + bv0, 0.0f));
                sm[FS_T + r0 * 132 + col + 1] = __float_as_uint(fmaxf(acc1[mt][nt][1] + bv1, 0.0f));
                sm[FS_T + r1 * 132 + col    ] = __float_as_uint(fmaxf(acc1[mt][nt][2] + bv0, 0.0f));
                sm[FS_T + r1 * 132 + col + 1] = __float_as_uint(fmaxf(acc1[mt][nt][3] + bv1, 0.0f));
            }
        }
        #pragma unroll
        for (int i = 0; i < 8; i++) {
            int idx = tid + i * 256;            // 0..2047
            int k = idx >> 4, q = idx & 15;
            *(uint4*)&sm[FS_B + k * 72 + q * 4] =
                *(const uint4*)&W5[(size_t)(cch * 128 + k) * 64 + q * 4];
        }
        __syncthreads();

        // ---- stage2: acc2 += t @ W5chunk  (128x64, K=128) ----
        #pragma unroll
        for (int ks = 0; ks < 16; ks++) {
            const int k0 = ks * 8;
            unsigned int a[2][4];
            #pragma unroll
            for (int mt = 0; mt < 2; mt++) {
                int mr = mrow + mt * 16;
                a[mt][0] = sm[FS_T + (mr + g    ) * 132 + k0 + tg    ];
                a[mt][1] = sm[FS_T + (mr + g + 8) * 132 + k0 + tg    ];
                a[mt][2] = sm[FS_T + (mr + g    ) * 132 + k0 + tg + 4];
                a[mt][3] = sm[FS_T + (mr + g + 8) * 132 + k0 + tg + 4];
            }
            #pragma unroll
            for (int nt = 0; nt < 4; nt++) {
                int nc = wn * 32 + nt * 8 + g;
                unsigned int b0 = sm[FS_B + (k0 + tg    ) * 72 + nc];
                unsigned int b1 = sm[FS_B + (k0 + tg + 4) * 72 + nc];
                #pragma unroll
                for (int mt = 0; mt < 2; mt++)
                    mma_tf32(acc2[mt][nt], a[mt][0], a[mt][1], a[mt][2], a[mt][3], b0, b1);
            }
        }
    }

    // ---- epilogue: + b5, store g3 ----
    #pragma unroll
    for (int nt = 0; nt < 4; nt++) {
        int col = wn * 32 + nt * 8 + 2 * tg;
        float bv0 = __uint_as_float(sm[FS_B5 + col]);
        float bv1 = __uint_as_float(sm[FS_B5 + col + 1]);
        #pragma unroll
        for (int mt = 0; mt < 2; mt++) {
            int r0 = n0 + mrow + mt * 16 + g;
            int r1 = r0 + 8;
            if (r0 < nrows) {
                float2 st; st.x = acc2[mt][nt][0] + bv0; st.y = acc2[mt][nt][1] + bv1;
                *(float2*)&C[(size_t)r0 * 64 + col] = st;
            }
            if (r1 < nrows) {
                float2 st; st.x = acc2[mt][nt][2] + bv0; st.y = acc2[mt][nt][3] + bv1;
                *(float2*)&C[(size_t)r1 * 64 + col] = st;
            }
        }
    }
}

// ---------------- proven fp32 register-tiled GEMM (used for 64->128 layer) ----------------
template<int K_TOT, int NOUT, bool RELU_OUT, bool UNMAP>
__global__ __launch_bounds__(256) void k_mlp_gemm(
    const void* __restrict__ Av,   // [nrows, K_TOT] float or mapped-uint
    const float* __restrict__ W,   // [K_TOT, NOUT]
    const float* __restrict__ b,   // [NOUT]
    float* __restrict__ C,         // [nrows, NOUT]
    int nrows)
{
    __shared__ float As[32][129];
    __shared__ float Bs[32][64];

    const int tid = threadIdx.x;
    const int n0 = blockIdx.x * 128;
    const int o0 = blockIdx.y * 64;

    const int ot = tid & 15;
    const int nt = tid >> 4;

    const float* Af = (const float*)Av;
    const unsigned int* Au = (const unsigned int*)Av;

    float acc[8][4];
    #pragma unroll
    for (int j = 0; j < 8; j++)
        #pragma unroll
        for (int q = 0; q < 4; q++) acc[j][q] = 0.0f;

    const int kk = tid & 31;
    const int nr = tid >> 5;
    const int oo = tid & 63;
    const int kb = tid >> 6;

    for (int k0 = 0; k0 < K_TOT; k0 += 32) {
        #pragma unroll
        for (int jj = 0; jj < 16; jj++) {
            int n = nr * 16 + jj;
            int row = n0 + n;
            float v = 0.0f;
            if (row < nrows) {
                size_t idx = (size_t)row * K_TOT + k0 + kk;
                v = UNMAP ? funmap(Au[idx]) : Af[idx];
            }
            As[kk][n] = v;
        }
        #pragma unroll
        for (int jj = 0; jj < 8; jj++) {
            int k = kb * 8 + jj;
            Bs[k][oo] = W[(size_t)(k0 + k) * NOUT + o0 + oo];
        }
        __syncthreads();

        #pragma unroll
        for (int k = 0; k < 32; k++) {
            float4 wv = *(const float4*)&Bs[k][ot * 4];
            float av[8];
            #pragma unroll
            for (int j = 0; j < 8; j++) av[j] = As[k][nt * 8 + j];
            #pragma unroll
            for (int j = 0; j < 8; j++) {
                acc[j][0] = fmaf(av[j], wv.x, acc[j][0]);
                acc[j][1] = fmaf(av[j], wv.y, acc[j][1]);
                acc[j][2] = fmaf(av[j], wv.z, acc[j][2]);
                acc[j][3] = fmaf(av[j], wv.w, acc[j][3]);
            }
        }
        __syncthreads();
    }

    float bias0 = b[o0 + ot * 4 + 0];
    float bias1 = b[o0 + ot * 4 + 1];
    float bias2 = b[o0 + ot * 4 + 2];
    float bias3 = b[o0 + ot * 4 + 3];
    #pragma unroll
    for (int j = 0; j < 8; j++) {
        int row = n0 + nt * 8 + j;
        if (row >= nrows) continue;
        float4 v;
        v.x = acc[j][0] + bias0;
        v.y = acc[j][1] + bias1;
        v.z = acc[j][2] + bias2;
        v.w = acc[j][3] + bias3;
        if (RELU_OUT) {
            v.x = fmaxf(v.x, 0.0f); v.y = fmaxf(v.y, 0.0f);
            v.z = fmaxf(v.z, 0.0f); v.w = fmaxf(v.w, 0.0f);
        }
        *(float4*)&C[(size_t)row * NOUT + o0 + ot * 4] = v;
    }
}

// ---------------- kernel: relu(g3) @ Wf + bf, then log_softmax ----------------
__global__ __launch_bounds__(256) void k_fc_softmax(
    const float* __restrict__ Wf,  // [64,40]
    const float* __restrict__ bf,  // [40]
    float* __restrict__ out)       // [N,40]
{
    __shared__ float sWf[64 * 40];
    __shared__ float sbf[40];
    for (int i = threadIdx.x; i < 64 * 40; i += blockDim.x) sWf[i] = Wf[i];
    for (int i = threadIdx.x; i < 40; i += blockDim.x) sbf[i] = bf[i];
    __syncthreads();

    int warp = threadIdx.x >> 5;
    int lane = threadIdx.x & 31;
    int node = blockIdx.x * 8 + warp;
    if (node >= N_NODES) return;

    const float* gp = g_g3 + (size_t)node * 64;
    float v0 = sbf[lane];
    float v1 = (lane < 8) ? sbf[lane + 32] : -FLT_MAX;

    for (int k = 0; k < 64; k++) {
        float a = fmaxf(gp[k], 0.0f);
        v0 = fmaf(a, sWf[k * 40 + lane], v0);
        if (lane < 8) v1 = fmaf(a, sWf[k * 40 + lane + 32], v1);
    }

    float m = fmaxf(v0, v1);
    #pragma unroll
    for (int off = 16; off > 0; off >>= 1)
        m = fmaxf(m, __shfl_xor_sync(0xFFFFFFFFu, m, off));

    float s = __expf(v0 - m) + ((lane < 8) ? __expf(v1 - m) : 0.0f);
    #pragma unroll
    for (int off = 16; off > 0; off >>= 1)
        s += __shfl_xor_sync(0xFFFFFFFFu, s, off);

    float ls = __logf(s);
    float* op = out + (size_t)node * 40;
    op[lane] = v0 - m - ls;
    if (lane < 8) op[lane + 32] = v1 - m - ls;
}

// ---------------- launcher ----------------
extern "C" void kernel_launch(void* const* d_in, const int* in_sizes, int n_in,
                              void* d_out, int out_size) {
    const float* x   = (const float*)d_in[0];
    const float* pos = (const float*)d_in[1];
    const int*   ei  = (const int*)d_in[2];
    const float* W1 = (const float*)d_in[3];
    const float* b1 = (const float*)d_in[4];
    const float* W2 = (const float*)d_in[5];
    const float* b2 = (const float*)d_in[6];
    const float* W3 = (const float*)d_in[7];
    const float* b3 = (const float*)d_in[8];
    const float* W4 = (const float*)d_in[9];
    const float* b4 = (const float*)d_in[10];
    const float* W5 = (const float*)d_in[11];
    const float* b5 = (const float*)d_in[12];
    const float* Wf = (const float*)d_in[13];
    const float* bf = (const float*)d_in[14];
    float* out = (float*)d_out;

    void* aggp = nullptr; void* g1 = nullptr; void* g3 = nullptr;
    cudaGetSymbolAddress(&aggp, g_agg_u);
    cudaGetSymbolAddress(&g1, g_g1);
    cudaGetSymbolAddress(&g3, g_g3);

    cudaFuncSetAttribute(k_fused_mid, cudaFuncAttributeMaxDynamicSharedMemorySize,
                         FS_WORDS * 4);

    // mapped-uint 0 is below every mapped float -> -inf init
    cudaMemsetAsync(aggp, 0, (size_t)N_NODES * 64 * sizeof(unsigned int));

    k_edge_mma<<<(N_MSG + 127) / 128, 256>>>(x, pos, ei, W1, b1, W2, b2);

    dim3 grd3((N_NODES + 127) / 128, 128 / 64);
    k_mlp_gemm<64, 128, true, true><<<grd3, 256>>>(aggp, W3, b3, (float*)g1, N_NODES);

    k_fused_mid<<<(N_NODES + 127) / 128, 256, FS_WORDS * 4>>>(
        (const float*)g1, W4, b4, W5, b5, (float*)g3, N_NODES);

    k_fc_softmax<<<(N_NODES + 7) / 8, 256>>>(Wf, bf, out);
}